// round 11
// baseline (speedup 1.0000x reference)
#include <cuda_runtime.h>
#include <math.h>
#include <stdint.h>

#define Bn 4
#define Tn 1024
#define Sn 64
#define En 128
#define NHn 4
#define DHn 32
#define FFn 256
#define Ln 3
#define Cn 4
#define SX 132            // row-major stride; 132 mod 32 = 4 -> conflict-free A-frags
#define SF 260            // FF stride; 260 mod 32 = 4
#define SP 68             // score stride; 68 mod 32 = 4
#define WST 136           // weight slab stride (OC=128); 136 mod 32 = 8 -> conflict-free B-frags
#define WST2 264          // weight slab stride (OC=256); 264 mod 32 = 8
#define WSLAB 2176        // floats per slab buffer: max(16*136, 8*264)
#define NTHREADS 512

// ---- tf32 / async helpers ----
__device__ __forceinline__ uint32_t totf(float f){
    uint32_t u; asm("cvt.rna.tf32.f32 %0, %1;" : "=r"(u) : "f"(f)); return u;
}
__device__ __forceinline__ void mma_tf32(float d[4], const uint32_t a[4], const uint32_t b[2]){
    asm("mma.sync.aligned.m16n8k8.row.col.f32.tf32.tf32.f32 "
        "{%0,%1,%2,%3},{%4,%5,%6,%7},{%8,%9},{%0,%1,%2,%3};"
        : "+f"(d[0]), "+f"(d[1]), "+f"(d[2]), "+f"(d[3])
        : "r"(a[0]), "r"(a[1]), "r"(a[2]), "r"(a[3]), "r"(b[0]), "r"(b[1]));
}
__device__ __forceinline__ void cpa16(float* s, const float* g){
    uint32_t sa = (uint32_t)__cvta_generic_to_shared(s);
    asm volatile("cp.async.cg.shared.global [%0], [%1], 16;" :: "r"(sa), "l"(g));
}
#define CP_COMMIT() asm volatile("cp.async.commit_group;")
#define CP_WAIT0()  asm volatile("cp.async.wait_group 0;")

__device__ __forceinline__ float gelu_tanh(float x){
    float x3 = x*x*x;
    float t = tanhf(0.7978845608028654f*(x + 0.044715f*x3));
    return 0.5f*x*(1.0f + t);
}

// ---- layernorm: 8 threads/row; row-major; dead rows zero-filled ----
__device__ __forceinline__ void layernorm_rm(const float* __restrict__ src,
        float* __restrict__ dst, const float* __restrict__ g,
        const float* __restrict__ b, int valid)
{
    const int t   = threadIdx.x;
    const int row = t >> 3;
    const int e   = t & 7;
    float* dr = dst + row*SX;
    if (row < valid){
        const unsigned gmask = 0xFFu << ((t & 31) & ~7);
        const float* xr = src + row*SX;
        float s = 0.f, s2 = 0.f;
        #pragma unroll
        for (int i = 0; i < 16; i++){
            float v = xr[e + 8*i];
            s += v; s2 = fmaf(v, v, s2);
        }
        s  += __shfl_xor_sync(gmask, s, 1);  s2 += __shfl_xor_sync(gmask, s2, 1);
        s  += __shfl_xor_sync(gmask, s, 2);  s2 += __shfl_xor_sync(gmask, s2, 2);
        s  += __shfl_xor_sync(gmask, s, 4);  s2 += __shfl_xor_sync(gmask, s2, 4);
        const float m    = s * 0.0078125f;
        const float rstd = rsqrtf(s2*0.0078125f - m*m + 1e-5f);
        #pragma unroll
        for (int i = 0; i < 16; i++){
            int c = e + 8*i;
            dr[c] = (xr[c] - m)*rstd*g[c] + b[c];
        }
    } else {
        #pragma unroll
        for (int i = 0; i < 16; i++) dr[e + 8*i] = 0.f;
    }
}

// ---- slab stagers: one 16B cp.async per thread ----
__device__ __forceinline__ void stage16x128(float* buf, const float* W, int k0){
    const int tid = threadIdx.x;
    const int r = tid >> 5, c = (tid & 31) << 2;
    cpa16(buf + r*WST + c, W + (size_t)(k0 + r)*128 + c);
}
__device__ __forceinline__ void stage8x256(float* buf, const float* W, int k0){
    const int tid = threadIdx.x;
    const int r = tid >> 6, c = (tid & 63) << 2;
    cpa16(buf + r*WST2 + c, W + (size_t)(k0 + r)*256 + c);
}

// ---- staged GEMM, OC=128: warp task 16m x 32n; W streamed in 16-row slabs ----
// MODE 0 = store, 1 = add into dst. All threads run bars/staging; compute guarded.
template<int IC, int SS_, int DS, int MODE>
__device__ __forceinline__ void gemm_staged128(const float* __restrict__ src,
        const float* __restrict__ W, const float* __restrict__ bias,
        float* __restrict__ dst, float* WS, int valid)
{
    const int tid = threadIdx.x;
    const int warp = tid >> 5, lane = tid & 31;
    const int g = lane >> 2, tig = lane & 3;
    const int m0 = (warp >> 2) * 16;
    const int n0 = (warp & 3) * 32;
    const bool live = (m0 < valid);
    const int NS = IC / 16;

    float d[4][4];
    if (live){
        #pragma unroll
        for (int nt = 0; nt < 4; nt++){
            const float2 bb = *(const float2*)(bias + n0 + nt*8 + 2*tig);
            d[nt][0] = bb.x; d[nt][1] = bb.y; d[nt][2] = bb.x; d[nt][3] = bb.y;
        }
    }
    stage16x128(WS, W, 0);
    CP_COMMIT();
    const float* s0 = src + (m0 + g)*SS_ + tig;
    const float* s1 = s0 + 8*SS_;

    #pragma unroll 1
    for (int s = 0; s < NS; s++){
        CP_WAIT0();
        __syncthreads();            // slab s visible; compute s-1 done -> buf reuse safe
        if (s + 1 < NS){
            stage16x128(WS + ((s+1)&1)*WSLAB, W, (s+1)*16);
            CP_COMMIT();
        }
        if (live){
            const float* buf = WS + (s&1)*WSLAB;
            #pragma unroll
            for (int k2 = 0; k2 < 2; k2++){
                const int k0 = s*16 + k2*8;
                const int kb = k2*8;
                uint32_t ua[4] = { totf(s0[k0]), totf(s1[k0]),
                                   totf(s0[k0+4]), totf(s1[k0+4]) };
                #pragma unroll
                for (int nt = 0; nt < 4; nt++){
                    const float* bp = buf + (kb + tig)*WST + n0 + g + nt*8;
                    uint32_t ub[2] = { totf(bp[0]), totf(bp[4*WST]) };
                    mma_tf32(d[nt], ua, ub);
                }
            }
        }
    }
    if (live){
        #pragma unroll
        for (int nt = 0; nt < 4; nt++){
            const int c  = n0 + nt*8 + 2*tig;
            float* p0 = dst + (m0 + g)*DS + c;
            float* p1 = dst + (m0 + g + 8)*DS + c;
            if (MODE == 0){
                *(float2*)p0 = make_float2(d[nt][0], d[nt][1]);
                *(float2*)p1 = make_float2(d[nt][2], d[nt][3]);
            } else {
                float2 x0 = *(float2*)p0, x1 = *(float2*)p1;
                x0.x += d[nt][0]; x0.y += d[nt][1]; *(float2*)p0 = x0;
                x1.x += d[nt][2]; x1.y += d[nt][3]; *(float2*)p1 = x1;
            }
        }
    }
}

// ---- staged w1: OC=256, gelu epilogue; 8-row x 256-col slabs; 2 n-tasks/warp ----
__device__ __forceinline__ void gemm_staged_w1(const float* __restrict__ src,
        const float* __restrict__ W, const float* __restrict__ bias,
        float* __restrict__ dst, float* WS, int valid)
{
    const int tid = threadIdx.x;
    const int warp = tid >> 5, lane = tid & 31;
    const int g = lane >> 2, tig = lane & 3;
    const int m0 = (warp >> 2) * 16;
    const int n0 = (warp & 3) * 32;
    const bool live = (m0 < valid);
    const int NS = En / 8;            // 16 slabs

    float d[2][4][4];
    if (live){
        #pragma unroll
        for (int t2 = 0; t2 < 2; t2++)
        #pragma unroll
        for (int nt = 0; nt < 4; nt++){
            const float2 bb = *(const float2*)(bias + n0 + t2*128 + nt*8 + 2*tig);
            d[t2][nt][0] = bb.x; d[t2][nt][1] = bb.y; d[t2][nt][2] = bb.x; d[t2][nt][3] = bb.y;
        }
    }
    stage8x256(WS, W, 0);
    CP_COMMIT();
    const float* s0 = src + (m0 + g)*SX + tig;
    const float* s1 = s0 + 8*SX;

    #pragma unroll 1
    for (int s = 0; s < NS; s++){
        CP_WAIT0();
        __syncthreads();
        if (s + 1 < NS){
            stage8x256(WS + ((s+1)&1)*WSLAB, W, (s+1)*8);
            CP_COMMIT();
        }
        if (live){
            const float* buf = WS + (s&1)*WSLAB;
            const int k0 = s*8;
            uint32_t ua[4] = { totf(s0[k0]), totf(s1[k0]),
                               totf(s0[k0+4]), totf(s1[k0+4]) };
            #pragma unroll
            for (int t2 = 0; t2 < 2; t2++)
            #pragma unroll
            for (int nt = 0; nt < 4; nt++){
                const float* bp = buf + tig*WST2 + n0 + t2*128 + g + nt*8;
                uint32_t ub[2] = { totf(bp[0]), totf(bp[4*WST2]) };
                mma_tf32(d[t2][nt], ua, ub);
            }
        }
    }
    if (live){
        #pragma unroll
        for (int t2 = 0; t2 < 2; t2++)
        #pragma unroll
        for (int nt = 0; nt < 4; nt++){
            const int c  = n0 + t2*128 + nt*8 + 2*tig;
            float* p0 = dst + (m0 + g)*SF + c;
            float* p1 = dst + (m0 + g + 8)*SF + c;
            *(float2*)p0 = make_float2(gelu_tanh(d[t2][nt][0]), gelu_tanh(d[t2][nt][1]));
            *(float2*)p1 = make_float2(gelu_tanh(d[t2][nt][2]), gelu_tanh(d[t2][nt][3]));
        }
    }
}

#define SMEM_FLOATS (5*Sn*SX + 2*Sn*16 + 2*Sn*SP + 2*WSLAB)
#define SMEM_BYTES  (SMEM_FLOATS*4)

__global__ void __launch_bounds__(NTHREADS, 1) rowinteraction_kernel(
    const float* __restrict__ emb,  const float* __restrict__ cls,
    const float* __restrict__ ln1g, const float* __restrict__ ln1b,
    const float* __restrict__ wq,   const float* __restrict__ bq,
    const float* __restrict__ wk,   const float* __restrict__ bk,
    const float* __restrict__ wv,   const float* __restrict__ bv,
    const float* __restrict__ wo,   const float* __restrict__ bo,
    const float* __restrict__ ln2g, const float* __restrict__ ln2b,
    const float* __restrict__ w1,   const float* __restrict__ b1,
    const float* __restrict__ w2,   const float* __restrict__ b2,
    const float* __restrict__ og,   const float* __restrict__ ob,
    const int*   __restrict__ dvec, float* __restrict__ out)
{
    extern __shared__ float smf[];
    float* X  = smf;                 // [64][132] residual
    float* H  = X  + Sn*SX;          // [64][132] ln out / attn out
    float* Qb = H  + Sn*SX;
    float* Kb = Qb + Sn*SX;
    float* Vb = Kb + Sn*SX;
    float* FF = Qb;                  // [64][260] overlays Q+K
    float* RC = Vb + Sn*SX;          // rope cos [64][16]
    float* RS = RC + Sn*16;
    float* SS = RS + Sn*16;          // scores, 2 heads x [64][68]
    float* WS = SS + 2*Sn*SP;        // weight slab double buffer, 2 x WSLAB

    const int tid   = threadIdx.x;
    const int warp  = tid >> 5;
    const int lane  = tid & 31;
    const int g     = lane >> 2;
    const int tig   = lane & 3;
    const int n     = blockIdx.x;
    const int bidx  = n >> 10;        // T = 1024
    const int valid = dvec[bidx] + Cn;          // 4..63
    const float scale = 0.17677669529663687f;   // 1/sqrt(32)

    for (int idx = tid; idx < Sn*16; idx += NTHREADS){
        int pos = idx >> 4, f = idx & 15;
        float inv = expf(-((float)(2*f) / (float)DHn) * logf(100000.0f));
        float ang = (float)pos * inv;
        RC[idx] = cosf(ang); RS[idx] = sinf(ang);
    }
    for (int idx = tid; idx < Sn*En; idx += NTHREADS){
        int r = idx >> 7, c = idx & 127;
        float v = (r < Cn) ? cls[r*En + c] : emb[((size_t)n*Sn + r)*En + c];
        X[r*SX + c] = v;
    }
    __syncthreads();

    for (int l = 0; l < Ln; ++l){
        layernorm_rm(X, H, ln1g + l*En, ln1b + l*En, valid);
        __syncthreads();
        gemm_staged128<En, SX, SX, 0>(H, wq + l*En*En, bq + l*En, Qb, WS, valid);
        __syncthreads();
        gemm_staged128<En, SX, SX, 0>(H, wk + l*En*En, bk + l*En, Kb, WS, valid);
        __syncthreads();
        gemm_staged128<En, SX, SX, 0>(H, wv + l*En*En, bv + l*En, Vb, WS, valid);
        __syncthreads();
        // RoPE on live rows + ZERO dead K/V rows
        for (int idx = tid; idx < Sn*NHn*16; idx += NTHREADS){
            int row = idx >> 6;
            if (row < valid){
                int hj = idx & 63; int h = hj >> 4; int j = hj & 15;
                float cc = RC[row*16 + j], ss = RS[row*16 + j];
                int o1 = row*SX + h*DHn + j, o2 = o1 + 16;
                float q1 = Qb[o1], q2 = Qb[o2];
                Qb[o1] = q1*cc - q2*ss;  Qb[o2] = q2*cc + q1*ss;
                float k1 = Kb[o1], k2 = Kb[o2];
                Kb[o1] = k1*cc - k2*ss;  Kb[o2] = k2*cc + k1*ss;
            } else {
                int c = (idx & 63) << 1;
                Kb[row*SX + c] = 0.f; Kb[row*SX + c + 1] = 0.f;
                Vb[row*SX + c] = 0.f; Vb[row*SX + c + 1] = 0.f;
            }
        }
        __syncthreads();

        // ---- attention via tensor cores; two head-pair passes ----
        for (int hp = 0; hp < 2; hp++){
            {   // S = Q K^T
                const int h2 = warp >> 3, mt = (warp >> 1) & 3, nh = warp & 1;
                const int qbase = (hp*2 + h2)*DHn;
                const int m0 = mt*16;
                if (m0 < valid){
                    float dS[4][4];
                    #pragma unroll
                    for (int nt = 0; nt < 4; nt++)
                        dS[nt][0] = dS[nt][1] = dS[nt][2] = dS[nt][3] = 0.f;
                    const float* q0 = Qb + (m0 + g)*SX + qbase;
                    const float* q1 = q0 + 8*SX;
                    #pragma unroll
                    for (int ks = 0; ks < 4; ks++){
                        const int k0 = ks*8;
                        uint32_t ua[4] = { totf(q0[k0+tig]), totf(q1[k0+tig]),
                                           totf(q0[k0+tig+4]), totf(q1[k0+tig+4]) };
                        #pragma unroll
                        for (int nt = 0; nt < 4; nt++){
                            const int n0 = nh*32 + nt*8;
                            if (n0 < valid){
                                const float* kp = Kb + (n0 + g)*SX + qbase + k0;
                                uint32_t ub[2] = { totf(kp[tig]), totf(kp[tig+4]) };
                                mma_tf32(dS[nt], ua, ub);
                            }
                        }
                    }
                    float* Sp = SS + h2*(Sn*SP);
                    #pragma unroll
                    for (int nt = 0; nt < 4; nt++){
                        const int n0 = nh*32 + nt*8;
                        if (n0 < valid){
                            float* p = Sp + (m0 + g)*SP + n0 + 2*tig;
                            *(float2*)p          = make_float2(dS[nt][0], dS[nt][1]);
                            *(float2*)(p + 8*SP) = make_float2(dS[nt][2], dS[nt][3]);
                        }
                    }
                }
            }
            __syncthreads();
            {   // softmax: normalized P; masked cols zeroed
                const int r   = tid >> 2;
                const int q4  = tid & 3;
                const int h2  = r >> 6, row = r & 63;
                if (row < valid){
                    const unsigned gmask = 0xFu << (lane & 28);
                    float* Sr = SS + h2*(Sn*SP) + row*SP;
                    float sv[16];
                    float m = -1e30f;
                    #pragma unroll
                    for (int i = 0; i < 16; i++){
                        int c = q4 + 4*i;
                        if (c < valid){ sv[i] = Sr[c]*scale; m = fmaxf(m, sv[i]); }
                        else sv[i] = 0.f;
                    }
                    m = fmaxf(m, __shfl_xor_sync(gmask, m, 1));
                    m = fmaxf(m, __shfl_xor_sync(gmask, m, 2));
                    float sum = 0.f;
                    #pragma unroll
                    for (int i = 0; i < 16; i++){
                        int c = q4 + 4*i;
                        float e = (c < valid) ? __expf(sv[i] - m) : 0.f;
                        sv[i] = e; sum += e;
                    }
                    sum += __shfl_xor_sync(gmask, sum, 1);
                    sum += __shfl_xor_sync(gmask, sum, 2);
                    const float inv = 1.0f / sum;
                    #pragma unroll
                    for (int i = 0; i < 16; i++) Sr[q4 + 4*i] = sv[i]*inv;
                }
            }
            __syncthreads();
            {   // O = P V -> H
                const int h2 = warp >> 3, mt = (warp >> 1) & 3, nh = warp & 1;
                const int obase = (hp*2 + h2)*DHn + nh*16;
                const int m0 = mt*16;
                if (m0 < valid){
                    float dO[2][4];
                    #pragma unroll
                    for (int nt = 0; nt < 2; nt++)
                        dO[nt][0] = dO[nt][1] = dO[nt][2] = dO[nt][3] = 0.f;
                    const float* Pp = SS + h2*(Sn*SP);
                    const float* p0 = Pp + (m0 + g)*SP;
                    const float* p1 = p0 + 8*SP;
                    const int NKS = (valid + 7) >> 3;
                    #pragma unroll 1
                    for (int ks = 0; ks < NKS; ks++){
                        const int k0 = ks*8;
                        uint32_t ua[4] = { totf(p0[k0+tig]), totf(p1[k0+tig]),
                                           totf(p0[k0+tig+4]), totf(p1[k0+tig+4]) };
                        #pragma unroll
                        for (int nt = 0; nt < 2; nt++){
                            const float* vp = Vb + (k0 + tig)*SX + obase + nt*8 + g;
                            uint32_t ub[2] = { totf(vp[0]), totf(vp[4*SX]) };
                            mma_tf32(dO[nt], ua, ub);
                        }
                    }
                    #pragma unroll
                    for (int nt = 0; nt < 2; nt++){
                        const int c = obase + nt*8 + 2*tig;
                        float* p = H + (m0 + g)*SX + c;
                        *(float2*)p          = make_float2(dO[nt][0], dO[nt][1]);
                        *(float2*)(p + 8*SX) = make_float2(dO[nt][2], dO[nt][3]);
                    }
                }
            }
            __syncthreads();
        }

        gemm_staged128<En, SX, SX, 1>(H, wo + l*En*En, bo + l*En, X, WS, valid);
        __syncthreads();
        layernorm_rm(X, H, ln2g + l*En, ln2b + l*En, valid);
        __syncthreads();
        gemm_staged_w1(H, w1 + l*En*FFn, b1 + l*FFn, FF, WS, valid);
        __syncthreads();
        gemm_staged128<FFn, SF, SX, 1>(FF, w2 + l*FFn*En, b2 + l*En, X, WS, valid);
        __syncthreads();
    }

    // Epilogue: out-layernorm rows 0..3, write (B,T,C*E)
    if (warp < Cn){
        const float4 xv = *(const float4*)(X + warp*SX + lane*4);
        float s  = xv.x + xv.y + xv.z + xv.w;
        float s2 = xv.x*xv.x + xv.y*xv.y + xv.z*xv.z + xv.w*xv.w;
        #pragma unroll
        for (int o = 16; o; o >>= 1){
            s  += __shfl_xor_sync(0xffffffffu, s,  o);
            s2 += __shfl_xor_sync(0xffffffffu, s2, o);
        }
        const float m    = s * 0.0078125f;
        const float rstd = rsqrtf(s2*0.0078125f - m*m + 1e-5f);
        const float4 gv  = *(const float4*)(og + lane*4);
        const float4 bv4 = *(const float4*)(ob + lane*4);
        float4 ovv;
        ovv.x = (xv.x - m)*rstd*gv.x + bv4.x;
        ovv.y = (xv.y - m)*rstd*gv.y + bv4.y;
        ovv.z = (xv.z - m)*rstd*gv.z + bv4.z;
        ovv.w = (xv.w - m)*rstd*gv.w + bv4.w;
        *(float4*)(out + (size_t)n*(Cn*En) + warp*En + lane*4) = ovv;
    }
}

extern "C" void kernel_launch(void* const* d_in, const int* in_sizes, int n_in,
                              void* d_out, int out_size)
{
    (void)in_sizes; (void)n_in; (void)out_size;
    cudaFuncSetAttribute(rowinteraction_kernel,
                         cudaFuncAttributeMaxDynamicSharedMemorySize, SMEM_BYTES);
    rowinteraction_kernel<<<Bn*Tn, NTHREADS, SMEM_BYTES>>>(
        (const float*)d_in[0],  (const float*)d_in[1],
        (const float*)d_in[2],  (const float*)d_in[3],
        (const float*)d_in[4],  (const float*)d_in[5],
        (const float*)d_in[6],  (const float*)d_in[7],
        (const float*)d_in[8],  (const float*)d_in[9],
        (const float*)d_in[10], (const float*)d_in[11],
        (const float*)d_in[12], (const float*)d_in[13],
        (const float*)d_in[14], (const float*)d_in[15],
        (const float*)d_in[16], (const float*)d_in[17],
        (const float*)d_in[18], (const float*)d_in[19],
        (const int*)d_in[20],   (float*)d_out);
}

// round 12
// speedup vs baseline: 1.5158x; 1.5158x over previous
#include <cuda_runtime.h>
#include <math.h>
#include <stdint.h>

#define Bn 4
#define Tn 1024
#define Sn 64
#define En 128
#define NHn 4
#define DHn 32
#define FFn 256
#define Ln 3
#define Cn 4
#define SX 132            // row-major stride; 132 mod 32 = 4 -> conflict-free A-frags
#define SF 260            // FF stride; 260 mod 32 = 4
#define SP 68             // score stride; 68 mod 32 = 4
#define NTHREADS 512

// packed weights: per layer {wq,wk,wv,wo: 8192 each, w1: 16384, w2: 16384} = 65536 float2
#define LSTRIDE 65536
__device__ float2 g_wpacked[3*LSTRIDE];

// ---- tf32 helpers ----
__device__ __forceinline__ uint32_t totf(float f){
    uint32_t u; asm("cvt.rna.tf32.f32 %0, %1;" : "=r"(u) : "f"(f)); return u;
}
__device__ __forceinline__ void mma_tf32(float d[4], const uint32_t a[4], const uint32_t b[2]){
    asm("mma.sync.aligned.m16n8k8.row.col.f32.tf32.tf32.f32 "
        "{%0,%1,%2,%3},{%4,%5,%6,%7},{%8,%9},{%0,%1,%2,%3};"
        : "+f"(d[0]), "+f"(d[1]), "+f"(d[2]), "+f"(d[3])
        : "r"(a[0]), "r"(a[1]), "r"(a[2]), "r"(a[3]), "r"(b[0]), "r"(b[1]));
}

__device__ __forceinline__ float gelu_tanh(float x){
    float x3 = x*x*x;
    float t = tanhf(0.7978845608028654f*(x + 0.044715f*x3));
    return 0.5f*x*(1.0f + t);
}

// ---- weight prep: tf32-round + fragment-pack. blockIdx.y = l*6 + w ----
__global__ void prep_weights(const float* __restrict__ wq, const float* __restrict__ wk,
                             const float* __restrict__ wv, const float* __restrict__ wo,
                             const float* __restrict__ w1, const float* __restrict__ w2)
{
    const int y = blockIdx.y;
    const int l = y / 6, w = y - 6*l;
    const float* W; int IC, OC; int off;
    switch (w){
        case 0: W = wq + l*En*En;  IC = En;  OC = En;  off = 0;     break;
        case 1: W = wk + l*En*En;  IC = En;  OC = En;  off = 8192;  break;
        case 2: W = wv + l*En*En;  IC = En;  OC = En;  off = 16384; break;
        case 3: W = wo + l*En*En;  IC = En;  OC = En;  off = 24576; break;
        case 4: W = w1 + l*En*FFn; IC = En;  OC = FFn; off = 32768; break;
        default:W = w2 + l*FFn*En; IC = FFn; OC = En;  off = 49152; break;
    }
    const int total = (IC >> 3) * OC * 4;
    float2* dst = g_wpacked + l*LSTRIDE + off;
    for (int idx = blockIdx.x*blockDim.x + threadIdx.x; idx < total;
         idx += gridDim.x*blockDim.x){
        const int tig = idx & 3;
        const int rem = idx >> 2;
        const int n   = rem % OC;
        const int ks  = rem / OC;
        const float a = W[(ks*8 + tig)*OC + n];
        const float b = W[(ks*8 + tig + 4)*OC + n];
        dst[idx] = make_float2(__uint_as_float(totf(a)), __uint_as_float(totf(b)));
    }
}

// ---- layernorm: 8 threads/row; row-major; dead rows zero-filled ----
__device__ __forceinline__ void layernorm_rm(const float* __restrict__ src,
        float* __restrict__ dst, const float* __restrict__ g,
        const float* __restrict__ b, int valid)
{
    const int t   = threadIdx.x;
    const int row = t >> 3;
    const int e   = t & 7;
    float* dr = dst + row*SX;
    if (row < valid){
        const unsigned gmask = 0xFFu << ((t & 31) & ~7);
        const float* xr = src + row*SX;
        float s = 0.f, s2 = 0.f;
        #pragma unroll
        for (int i = 0; i < 16; i++){
            float v = xr[e + 8*i];
            s += v; s2 = fmaf(v, v, s2);
        }
        s  += __shfl_xor_sync(gmask, s, 1);  s2 += __shfl_xor_sync(gmask, s2, 1);
        s  += __shfl_xor_sync(gmask, s, 2);  s2 += __shfl_xor_sync(gmask, s2, 2);
        s  += __shfl_xor_sync(gmask, s, 4);  s2 += __shfl_xor_sync(gmask, s2, 4);
        const float m    = s * 0.0078125f;
        const float rstd = rsqrtf(s2*0.0078125f - m*m + 1e-5f);
        #pragma unroll
        for (int i = 0; i < 16; i++){
            int c = e + 8*i;
            dr[c] = (xr[c] - m)*rstd*g[c] + b[c];
        }
    } else {
        #pragma unroll
        for (int i = 0; i < 16; i++) dr[e + 8*i] = 0.f;
    }
}

// ---- tensor-core GEMM warp tile on PACKED weights: 16m x 32n, one LDG.64/frag ----
template<int IC, int OC, int SS, int DS, int MODE>
__device__ __forceinline__ void mma_tile_p(const float* __restrict__ src,
        const float2* __restrict__ Wp, const float* __restrict__ bias,
        float* __restrict__ dst, int m0, int n0)
{
    const int lane = threadIdx.x & 31;
    const int g    = lane >> 2;
    const int tig  = lane & 3;
    const int NK   = IC / 8;

    float d[4][4];
    #pragma unroll
    for (int nt = 0; nt < 4; nt++){
        const float2 bb = *(const float2*)(bias + n0 + nt*8 + 2*tig);
        d[nt][0] = bb.x; d[nt][1] = bb.y; d[nt][2] = bb.x; d[nt][3] = bb.y;
    }

    const float* s0 = src + (m0 + g)*SS + tig;
    const float* s1 = src + (m0 + g + 8)*SS + tig;
    const float2* Wb = Wp + (size_t)(n0 + g)*4 + tig;   // + ks*OC*4 + nt*32

    float aC[4]; float2 bC[4];
    aC[0] = s0[0]; aC[1] = s1[0]; aC[2] = s0[4]; aC[3] = s1[4];
    #pragma unroll
    for (int nt = 0; nt < 4; nt++) bC[nt] = __ldg(Wb + nt*32);

    #pragma unroll 1
    for (int ks = 0; ks < NK; ks++){
        const int k1 = (ks + 1 < NK) ? (ks + 1)*8 : ks*8;
        const float2* Wn = Wb + (size_t)((ks + 1 < NK) ? (ks + 1) : ks)*OC*4;
        float aN[4]; float2 bN[4];
        aN[0] = s0[k1]; aN[1] = s1[k1]; aN[2] = s0[k1+4]; aN[3] = s1[k1+4];
        #pragma unroll
        for (int nt = 0; nt < 4; nt++) bN[nt] = __ldg(Wn + nt*32);
        uint32_t ua[4];
        #pragma unroll
        for (int i = 0; i < 4; i++) ua[i] = totf(aC[i]);
        #pragma unroll
        for (int nt = 0; nt < 4; nt++){
            uint32_t ub[2] = { __float_as_uint(bC[nt].x), __float_as_uint(bC[nt].y) };
            mma_tf32(d[nt], ua, ub);
        }
        #pragma unroll
        for (int i = 0; i < 4; i++) aC[i] = aN[i];
        #pragma unroll
        for (int nt = 0; nt < 4; nt++) bC[nt] = bN[nt];
    }

    #pragma unroll
    for (int nt = 0; nt < 4; nt++){
        const int c  = n0 + nt*8 + 2*tig;
        float* p0 = dst + (m0 + g)*DS + c;
        float* p1 = dst + (m0 + g + 8)*DS + c;
        if (MODE == 0){
            *(float2*)p0 = make_float2(d[nt][0], d[nt][1]);
            *(float2*)p1 = make_float2(d[nt][2], d[nt][3]);
        } else if (MODE == 1){
            float2 x0 = *(float2*)p0, x1 = *(float2*)p1;
            x0.x += d[nt][0]; x0.y += d[nt][1]; *(float2*)p0 = x0;
            x1.x += d[nt][2]; x1.y += d[nt][3]; *(float2*)p1 = x1;
        } else {
            *(float2*)p0 = make_float2(gelu_tanh(d[nt][0]), gelu_tanh(d[nt][1]));
            *(float2*)p1 = make_float2(gelu_tanh(d[nt][2]), gelu_tanh(d[nt][3]));
        }
    }
}

#define SMEM_FLOATS (5*Sn*SX + 2*Sn*16 + 2*Sn*SP)
#define SMEM_BYTES  (SMEM_FLOATS*4)

__global__ void __launch_bounds__(NTHREADS, 1) rowinteraction_kernel(
    const float* __restrict__ emb,  const float* __restrict__ cls,
    const float* __restrict__ ln1g, const float* __restrict__ ln1b,
    const float* __restrict__ bq,   const float* __restrict__ bk,
    const float* __restrict__ bv,   const float* __restrict__ bo,
    const float* __restrict__ ln2g, const float* __restrict__ ln2b,
    const float* __restrict__ b1,   const float* __restrict__ b2,
    const float* __restrict__ og,   const float* __restrict__ ob,
    const int*   __restrict__ dvec, float* __restrict__ out)
{
    extern __shared__ float smf[];
    float* X  = smf;                 // [64][132] residual
    float* H  = X  + Sn*SX;          // [64][132] ln out / attn out
    float* Qb = H  + Sn*SX;
    float* Kb = Qb + Sn*SX;
    float* Vb = Kb + Sn*SX;
    float* FF = Qb;                  // [64][260] overlays Q+K
    float* RC = Vb + Sn*SX;          // rope cos [64][16]
    float* RS = RC + Sn*16;
    float* SS = RS + Sn*16;          // scores, 2 heads x [64][68]

    const int tid   = threadIdx.x;
    const int warp  = tid >> 5;
    const int lane  = tid & 31;
    const int g     = lane >> 2;
    const int tig   = lane & 3;
    const int n     = blockIdx.x;
    const int bidx  = n >> 10;        // T = 1024
    const int valid = dvec[bidx] + Cn;          // 4..63
    const float scale = 0.17677669529663687f;   // 1/sqrt(32)

    for (int idx = tid; idx < Sn*16; idx += NTHREADS){
        int pos = idx >> 4, f = idx & 15;
        float inv = expf(-((float)(2*f) / (float)DHn) * logf(100000.0f));
        float ang = (float)pos * inv;
        RC[idx] = cosf(ang); RS[idx] = sinf(ang);
    }
    for (int idx = tid; idx < Sn*En; idx += NTHREADS){
        int r = idx >> 7, c = idx & 127;
        float v = (r < Cn) ? cls[r*En + c] : emb[((size_t)n*Sn + r)*En + c];
        X[r*SX + c] = v;
    }
    __syncthreads();

    const int mtw = warp >> 2;        // dense-GEMM m-tile
    const int ncw = warp & 3;         // dense-GEMM n-chunk

    for (int l = 0; l < Ln; ++l){
        const float2* WL = g_wpacked + l*LSTRIDE;
        layernorm_rm(X, H, ln1g + l*En, ln1b + l*En, valid);
        __syncthreads();
        {   // fused QKV: 3 rotated tasks per warp (packed weights)
            const float2* Ws[3] = { WL, WL + 8192, WL + 16384 };
            const float*  bs[3] = { bq + l*En, bk + l*En, bv + l*En };
            float* ds[3]        = { Qb, Kb, Vb };
            #pragma unroll
            for (int i = 0; i < 3; i++){
                const int mt = (mtw + i) & 3;
                if (mt*16 < valid)
                    mma_tile_p<En, En, SX, SX, 0>(H, Ws[i], bs[i], ds[i], mt*16, ncw*32);
            }
        }
        __syncthreads();
        // RoPE on live rows + ZERO dead K/V rows
        for (int idx = tid; idx < Sn*NHn*16; idx += NTHREADS){
            int row = idx >> 6;
            if (row < valid){
                int hj = idx & 63; int h = hj >> 4; int j = hj & 15;
                float cc = RC[row*16 + j], ss = RS[row*16 + j];
                int o1 = row*SX + h*DHn + j, o2 = o1 + 16;
                float q1 = Qb[o1], q2 = Qb[o2];
                Qb[o1] = q1*cc - q2*ss;  Qb[o2] = q2*cc + q1*ss;
                float k1 = Kb[o1], k2 = Kb[o2];
                Kb[o1] = k1*cc - k2*ss;  Kb[o2] = k2*cc + k1*ss;
            } else {
                int c = (idx & 63) << 1;
                Kb[row*SX + c] = 0.f; Kb[row*SX + c + 1] = 0.f;
                Vb[row*SX + c] = 0.f; Vb[row*SX + c + 1] = 0.f;
            }
        }
        __syncthreads();

        // ---- attention via tensor cores; two head-pair passes ----
        for (int hp = 0; hp < 2; hp++){
            {   // S = Q K^T
                const int h2 = warp >> 3, mt = (warp >> 1) & 3, nh = warp & 1;
                const int qbase = (hp*2 + h2)*DHn;
                const int m0 = mt*16;
                if (m0 < valid){
                    float dS[4][4];
                    #pragma unroll
                    for (int nt = 0; nt < 4; nt++)
                        dS[nt][0] = dS[nt][1] = dS[nt][2] = dS[nt][3] = 0.f;
                    const float* q0 = Qb + (m0 + g)*SX + qbase;
                    const float* q1 = q0 + 8*SX;
                    #pragma unroll
                    for (int ks = 0; ks < 4; ks++){
                        const int k0 = ks*8;
                        uint32_t ua[4] = { totf(q0[k0+tig]), totf(q1[k0+tig]),
                                           totf(q0[k0+tig+4]), totf(q1[k0+tig+4]) };
                        #pragma unroll
                        for (int nt = 0; nt < 4; nt++){
                            const int n0 = nh*32 + nt*8;
                            if (n0 < valid){
                                const float* kp = Kb + (n0 + g)*SX + qbase + k0;
                                uint32_t ub[2] = { totf(kp[tig]), totf(kp[tig+4]) };
                                mma_tf32(dS[nt], ua, ub);
                            }
                        }
                    }
                    float* Sp = SS + h2*(Sn*SP);
                    #pragma unroll
                    for (int nt = 0; nt < 4; nt++){
                        const int n0 = nh*32 + nt*8;
                        if (n0 < valid){
                            float* p = Sp + (m0 + g)*SP + n0 + 2*tig;
                            *(float2*)p          = make_float2(dS[nt][0], dS[nt][1]);
                            *(float2*)(p + 8*SP) = make_float2(dS[nt][2], dS[nt][3]);
                        }
                    }
                }
            }
            __syncthreads();
            {   // softmax: normalized P; masked cols zeroed
                const int r   = tid >> 2;
                const int q4  = tid & 3;
                const int h2  = r >> 6, row = r & 63;
                if (row < valid){
                    const unsigned gmask = 0xFu << (lane & 28);
                    float* Sr = SS + h2*(Sn*SP) + row*SP;
                    float sv[16];
                    float m = -1e30f;
                    #pragma unroll
                    for (int i = 0; i < 16; i++){
                        int c = q4 + 4*i;
                        if (c < valid){ sv[i] = Sr[c]*scale; m = fmaxf(m, sv[i]); }
                        else sv[i] = 0.f;
                    }
                    m = fmaxf(m, __shfl_xor_sync(gmask, m, 1));
                    m = fmaxf(m, __shfl_xor_sync(gmask, m, 2));
                    float sum = 0.f;
                    #pragma unroll
                    for (int i = 0; i < 16; i++){
                        int c = q4 + 4*i;
                        float e = (c < valid) ? __expf(sv[i] - m) : 0.f;
                        sv[i] = e; sum += e;
                    }
                    sum += __shfl_xor_sync(gmask, sum, 1);
                    sum += __shfl_xor_sync(gmask, sum, 2);
                    const float inv = 1.0f / sum;
                    #pragma unroll
                    for (int i = 0; i < 16; i++) Sr[q4 + 4*i] = sv[i]*inv;
                }
            }
            __syncthreads();
            {   // O = P V -> H
                const int h2 = warp >> 3, mt = (warp >> 1) & 3, nh = warp & 1;
                const int obase = (hp*2 + h2)*DHn + nh*16;
                const int m0 = mt*16;
                if (m0 < valid){
                    float dO[2][4];
                    #pragma unroll
                    for (int nt = 0; nt < 2; nt++)
                        dO[nt][0] = dO[nt][1] = dO[nt][2] = dO[nt][3] = 0.f;
                    const float* Pp = SS + h2*(Sn*SP);
                    const float* p0 = Pp + (m0 + g)*SP;
                    const float* p1 = p0 + 8*SP;
                    const int NKS = (valid + 7) >> 3;
                    #pragma unroll 1
                    for (int ks = 0; ks < NKS; ks++){
                        const int k0 = ks*8;
                        uint32_t ua[4] = { totf(p0[k0+tig]), totf(p1[k0+tig]),
                                           totf(p0[k0+tig+4]), totf(p1[k0+tig+4]) };
                        #pragma unroll
                        for (int nt = 0; nt < 2; nt++){
                            const float* vp = Vb + (k0 + tig)*SX + obase + nt*8 + g;
                            uint32_t ub[2] = { totf(vp[0]), totf(vp[4*SX]) };
                            mma_tf32(dO[nt], ua, ub);
                        }
                    }
                    #pragma unroll
                    for (int nt = 0; nt < 2; nt++){
                        const int c = obase + nt*8 + 2*tig;
                        float* p = H + (m0 + g)*SX + c;
                        *(float2*)p          = make_float2(dO[nt][0], dO[nt][1]);
                        *(float2*)(p + 8*SX) = make_float2(dO[nt][2], dO[nt][3]);
                    }
                }
            }
            __syncthreads();
        }

        if (mtw*16 < valid)           // x += o @ wo + bo
            mma_tile_p<En, En, SX, SX, 1>(H, WL + 24576, bo + l*En, X, mtw*16, ncw*32);
        __syncthreads();
        layernorm_rm(X, H, ln2g + l*En, ln2b + l*En, valid);
        __syncthreads();
        #pragma unroll
        for (int i = 0; i < 2; i++){  // gelu(h2 @ w1 + b1) -> FF
            const int mt = (mtw + 2*i) & 3;
            if (mt*16 < valid)
                mma_tile_p<En, FFn, SX, SF, 2>(H, WL + 32768, b1 + l*FFn, FF,
                                               mt*16, (ncw + 4*i)*32);
        }
        __syncthreads();
        if (mtw*16 < valid)           // x += ff @ w2 + b2
            mma_tile_p<FFn, En, SF, SX, 1>(FF, WL + 49152, b2 + l*En, X, mtw*16, ncw*32);
        __syncthreads();
    }

    // Epilogue: out-layernorm rows 0..3, write (B,T,C*E)
    if (warp < Cn){
        const float4 xv = *(const float4*)(X + warp*SX + lane*4);
        float s  = xv.x + xv.y + xv.z + xv.w;
        float s2 = xv.x*xv.x + xv.y*xv.y + xv.z*xv.z + xv.w*xv.w;
        #pragma unroll
        for (int o = 16; o; o >>= 1){
            s  += __shfl_xor_sync(0xffffffffu, s,  o);
            s2 += __shfl_xor_sync(0xffffffffu, s2, o);
        }
        const float m    = s * 0.0078125f;
        const float rstd = rsqrtf(s2*0.0078125f - m*m + 1e-5f);
        const float4 gv  = *(const float4*)(og + lane*4);
        const float4 bv4 = *(const float4*)(ob + lane*4);
        float4 ovv;
        ovv.x = (xv.x - m)*rstd*gv.x + bv4.x;
        ovv.y = (xv.y - m)*rstd*gv.y + bv4.y;
        ovv.z = (xv.z - m)*rstd*gv.z + bv4.z;
        ovv.w = (xv.w - m)*rstd*gv.w + bv4.w;
        *(float4*)(out + (size_t)n*(Cn*En) + warp*En + lane*4) = ovv;
    }
}

extern "C" void kernel_launch(void* const* d_in, const int* in_sizes, int n_in,
                              void* d_out, int out_size)
{
    (void)in_sizes; (void)n_in; (void)out_size;
    // 1) pack + tf32-round weights into __device__ scratch (graph-capturable)
    prep_weights<<<dim3(32, 18), 256>>>(
        (const float*)d_in[4],  (const float*)d_in[6],  (const float*)d_in[8],
        (const float*)d_in[10], (const float*)d_in[14], (const float*)d_in[16]);
    // 2) main fused kernel
    cudaFuncSetAttribute(rowinteraction_kernel,
                         cudaFuncAttributeMaxDynamicSharedMemorySize, SMEM_BYTES);
    rowinteraction_kernel<<<Bn*Tn, NTHREADS, SMEM_BYTES>>>(
        (const float*)d_in[0],  (const float*)d_in[1],
        (const float*)d_in[2],  (const float*)d_in[3],
        (const float*)d_in[5],  (const float*)d_in[7],
        (const float*)d_in[9],  (const float*)d_in[11],
        (const float*)d_in[12], (const float*)d_in[13],
        (const float*)d_in[15], (const float*)d_in[17],
        (const float*)d_in[18], (const float*)d_in[19],
        (const int*)d_in[20],   (float*)d_out);
}

// round 13
// speedup vs baseline: 1.5515x; 1.0236x over previous
#include <cuda_runtime.h>
#include <math.h>
#include <stdint.h>

#define Bn 4
#define Tn 1024
#define Sn 64
#define En 128
#define NHn 4
#define DHn 32
#define FFn 256
#define Ln 3
#define Cn 4
#define SX 132            // row-major stride; 132 mod 32 = 4 -> conflict-free A-frags
#define SF 260            // FF stride; 260 mod 32 = 4
#define SP 68             // score stride; 68 mod 32 = 4
#define NTHREADS 512

// packed weights: per layer {wq,wk,wv,wo: 8192 each, w1: 16384, w2: 16384} = 65536 float2
#define LSTRIDE 65536
__device__ float2 g_wpacked[3*LSTRIDE];

// ---- tf32 helpers ----
__device__ __forceinline__ uint32_t totf(float f){
    uint32_t u; asm("cvt.rna.tf32.f32 %0, %1;" : "=r"(u) : "f"(f)); return u;
}
__device__ __forceinline__ float rtf(float f){ return __uint_as_float(totf(f)); }
__device__ __forceinline__ void mma_tf32(float d[4], const uint32_t a[4], const uint32_t b[2]){
    asm("mma.sync.aligned.m16n8k8.row.col.f32.tf32.tf32.f32 "
        "{%0,%1,%2,%3},{%4,%5,%6,%7},{%8,%9},{%0,%1,%2,%3};"
        : "+f"(d[0]), "+f"(d[1]), "+f"(d[2]), "+f"(d[3])
        : "r"(a[0]), "r"(a[1]), "r"(a[2]), "r"(a[3]), "r"(b[0]), "r"(b[1]));
}

__device__ __forceinline__ float gelu_tanh(float x){
    float x3 = x*x*x;
    float t = tanhf(0.7978845608028654f*(x + 0.044715f*x3));
    return 0.5f*x*(1.0f + t);
}

// ---- weight prep: tf32-round + fragment-pack. blockIdx.y = l*6 + w ----
__global__ void prep_weights(const float* __restrict__ wq, const float* __restrict__ wk,
                             const float* __restrict__ wv, const float* __restrict__ wo,
                             const float* __restrict__ w1, const float* __restrict__ w2)
{
    const int y = blockIdx.y;
    const int l = y / 6, w = y - 6*l;
    const float* W; int IC, OC; int off;
    switch (w){
        case 0: W = wq + l*En*En;  IC = En;  OC = En;  off = 0;     break;
        case 1: W = wk + l*En*En;  IC = En;  OC = En;  off = 8192;  break;
        case 2: W = wv + l*En*En;  IC = En;  OC = En;  off = 16384; break;
        case 3: W = wo + l*En*En;  IC = En;  OC = En;  off = 24576; break;
        case 4: W = w1 + l*En*FFn; IC = En;  OC = FFn; off = 32768; break;
        default:W = w2 + l*FFn*En; IC = FFn; OC = En;  off = 49152; break;
    }
    const int total = (IC >> 3) * OC * 4;
    float2* dst = g_wpacked + l*LSTRIDE + off;
    for (int idx = blockIdx.x*blockDim.x + threadIdx.x; idx < total;
         idx += gridDim.x*blockDim.x){
        const int tig = idx & 3;
        const int rem = idx >> 2;
        const int n   = rem % OC;
        const int ks  = rem / OC;
        const float a = W[(ks*8 + tig)*OC + n];
        const float b = W[(ks*8 + tig + 4)*OC + n];
        dst[idx] = make_float2(__uint_as_float(totf(a)), __uint_as_float(totf(b)));
    }
}

// ---- layernorm: 8 threads/row; output tf32-ROUNDED (GEMM input); dead rows zeroed ----
__device__ __forceinline__ void layernorm_rm(const float* __restrict__ src,
        float* __restrict__ dst, const float* __restrict__ g,
        const float* __restrict__ b, int valid)
{
    const int t   = threadIdx.x;
    const int row = t >> 3;
    const int e   = t & 7;
    float* dr = dst + row*SX;
    if (row < valid){
        const unsigned gmask = 0xFFu << ((t & 31) & ~7);
        const float* xr = src + row*SX;
        float s = 0.f, s2 = 0.f;
        #pragma unroll
        for (int i = 0; i < 16; i++){
            float v = xr[e + 8*i];
            s += v; s2 = fmaf(v, v, s2);
        }
        s  += __shfl_xor_sync(gmask, s, 1);  s2 += __shfl_xor_sync(gmask, s2, 1);
        s  += __shfl_xor_sync(gmask, s, 2);  s2 += __shfl_xor_sync(gmask, s2, 2);
        s  += __shfl_xor_sync(gmask, s, 4);  s2 += __shfl_xor_sync(gmask, s2, 4);
        const float m    = s * 0.0078125f;
        const float rstd = rsqrtf(s2*0.0078125f - m*m + 1e-5f);
        #pragma unroll
        for (int i = 0; i < 16; i++){
            int c = e + 8*i;
            dr[c] = rtf((xr[c] - m)*rstd*g[c] + b[c]);
        }
    } else {
        #pragma unroll
        for (int i = 0; i < 16; i++) dr[e + 8*i] = 0.f;
    }
}

// ---- tensor-core GEMM warp tile on PACKED weights + PRE-ROUNDED src ----
// MODE 0 = store, 1 = add into dst (full fp32), 2 = gelu store.
// ROPE: rotate (j, j+16) head pairs in registers before store. ROUND: tf32-round stores.
template<int IC, int OC, int SS, int DS, int MODE, int ROPE, int ROUND>
__device__ __forceinline__ void mma_tile_p(const float* __restrict__ src,
        const float2* __restrict__ Wp, const float* __restrict__ bias,
        float* __restrict__ dst, int m0, int n0,
        const float* __restrict__ RCp, const float* __restrict__ RSp)
{
    const int lane = threadIdx.x & 31;
    const int g    = lane >> 2;
    const int tig  = lane & 3;
    const int NK   = IC / 8;

    float d[4][4];
    #pragma unroll
    for (int nt = 0; nt < 4; nt++){
        const float2 bb = *(const float2*)(bias + n0 + nt*8 + 2*tig);
        d[nt][0] = bb.x; d[nt][1] = bb.y; d[nt][2] = bb.x; d[nt][3] = bb.y;
    }

    const float* s0 = src + (m0 + g)*SS + tig;
    const float* s1 = src + (m0 + g + 8)*SS + tig;
    const float2* Wb = Wp + (size_t)(n0 + g)*4 + tig;

    float aC[4]; float2 bC[4];
    aC[0] = s0[0]; aC[1] = s1[0]; aC[2] = s0[4]; aC[3] = s1[4];
    #pragma unroll
    for (int nt = 0; nt < 4; nt++) bC[nt] = __ldg(Wb + nt*32);

    #pragma unroll 1
    for (int ks = 0; ks < NK; ks++){
        const int k1 = (ks + 1 < NK) ? (ks + 1)*8 : ks*8;
        const float2* Wn = Wb + (size_t)((ks + 1 < NK) ? (ks + 1) : ks)*OC*4;
        float aN[4]; float2 bN[4];
        aN[0] = s0[k1]; aN[1] = s1[k1]; aN[2] = s0[k1+4]; aN[3] = s1[k1+4];
        #pragma unroll
        for (int nt = 0; nt < 4; nt++) bN[nt] = __ldg(Wn + nt*32);
        uint32_t ua[4];
        #pragma unroll
        for (int i = 0; i < 4; i++) ua[i] = __float_as_uint(aC[i]);   // pre-rounded
        #pragma unroll
        for (int nt = 0; nt < 4; nt++){
            uint32_t ub[2] = { __float_as_uint(bC[nt].x), __float_as_uint(bC[nt].y) };
            mma_tf32(d[nt], ua, ub);
        }
        #pragma unroll
        for (int i = 0; i < 4; i++) aC[i] = aN[i];
        #pragma unroll
        for (int nt = 0; nt < 4; nt++) bC[nt] = bN[nt];
    }

    if (ROPE){
        // n-chunk == one head; pairs (j, j+16) are (d[nt], d[nt+2]), nt in {0,1}
        #pragma unroll
        for (int nt = 0; nt < 2; nt++){
            const int j = nt*8 + 2*tig;
            const float2 c0 = *(const float2*)(RCp + (m0 + g)*16 + j);
            const float2 n0v= *(const float2*)(RSp + (m0 + g)*16 + j);
            const float2 c1 = *(const float2*)(RCp + (m0 + g + 8)*16 + j);
            const float2 n1v= *(const float2*)(RSp + (m0 + g + 8)*16 + j);
            float t1, t2;
            t1 = d[nt][0]; t2 = d[nt+2][0];
            d[nt][0] = t1*c0.x - t2*n0v.x;  d[nt+2][0] = t2*c0.x + t1*n0v.x;
            t1 = d[nt][1]; t2 = d[nt+2][1];
            d[nt][1] = t1*c0.y - t2*n0v.y;  d[nt+2][1] = t2*c0.y + t1*n0v.y;
            t1 = d[nt][2]; t2 = d[nt+2][2];
            d[nt][2] = t1*c1.x - t2*n1v.x;  d[nt+2][2] = t2*c1.x + t1*n1v.x;
            t1 = d[nt][3]; t2 = d[nt+2][3];
            d[nt][3] = t1*c1.y - t2*n1v.y;  d[nt+2][3] = t2*c1.y + t1*n1v.y;
        }
    }

    #pragma unroll
    for (int nt = 0; nt < 4; nt++){
        const int c  = n0 + nt*8 + 2*tig;
        float* p0 = dst + (m0 + g)*DS + c;
        float* p1 = dst + (m0 + g + 8)*DS + c;
        if (MODE == 0){
            if (ROUND){
                *(float2*)p0 = make_float2(rtf(d[nt][0]), rtf(d[nt][1]));
                *(float2*)p1 = make_float2(rtf(d[nt][2]), rtf(d[nt][3]));
            } else {
                *(float2*)p0 = make_float2(d[nt][0], d[nt][1]);
                *(float2*)p1 = make_float2(d[nt][2], d[nt][3]);
            }
        } else if (MODE == 1){
            float2 x0 = *(float2*)p0, x1 = *(float2*)p1;
            x0.x += d[nt][0]; x0.y += d[nt][1]; *(float2*)p0 = x0;
            x1.x += d[nt][2]; x1.y += d[nt][3]; *(float2*)p1 = x1;
        } else {
            *(float2*)p0 = make_float2(rtf(gelu_tanh(d[nt][0])), rtf(gelu_tanh(d[nt][1])));
            *(float2*)p1 = make_float2(rtf(gelu_tanh(d[nt][2])), rtf(gelu_tanh(d[nt][3])));
        }
    }
}

#define SMEM_FLOATS (5*Sn*SX + 2*Sn*16 + 2*Sn*SP)
#define SMEM_BYTES  (SMEM_FLOATS*4)

__global__ void __launch_bounds__(NTHREADS, 1) rowinteraction_kernel(
    const float* __restrict__ emb,  const float* __restrict__ cls,
    const float* __restrict__ ln1g, const float* __restrict__ ln1b,
    const float* __restrict__ bq,   const float* __restrict__ bk,
    const float* __restrict__ bv,   const float* __restrict__ bo,
    const float* __restrict__ ln2g, const float* __restrict__ ln2b,
    const float* __restrict__ b1,   const float* __restrict__ b2,
    const float* __restrict__ og,   const float* __restrict__ ob,
    const int*   __restrict__ dvec, float* __restrict__ out)
{
    extern __shared__ float smf[];
    float* X  = smf;                 // [64][132] residual (full fp32)
    float* H  = X  + Sn*SX;          // [64][132] ln/attn out (tf32-rounded)
    float* Qb = H  + Sn*SX;
    float* Kb = Qb + Sn*SX;
    float* Vb = Kb + Sn*SX;
    float* FF = Qb;                  // [64][260] overlays Q+K
    float* RC = Vb + Sn*SX;          // rope cos [64][16]
    float* RS = RC + Sn*16;
    float* SS = RS + Sn*16;          // scores, 2 heads x [64][68]

    const int tid   = threadIdx.x;
    const int warp  = tid >> 5;
    const int lane  = tid & 31;
    const int g     = lane >> 2;
    const int tig   = lane & 3;
    const int n     = blockIdx.x;
    const int bidx  = n >> 10;        // T = 1024
    const int valid = dvec[bidx] + Cn;          // 4..63
    const float scale = 0.17677669529663687f;   // 1/sqrt(32)

    for (int idx = tid; idx < Sn*16; idx += NTHREADS){
        int pos = idx >> 4, f = idx & 15;
        float inv = expf(-((float)(2*f) / (float)DHn) * logf(100000.0f));
        float ang = (float)pos * inv;
        RC[idx] = cosf(ang); RS[idx] = sinf(ang);
    }
    for (int idx = tid; idx < Sn*En; idx += NTHREADS){
        int r = idx >> 7, c = idx & 127;
        float v = (r < Cn) ? cls[r*En + c] : emb[((size_t)n*Sn + r)*En + c];
        X[r*SX + c] = v;
    }
    __syncthreads();

    const int mtw = warp >> 2;        // dense-GEMM m-tile
    const int ncw = warp & 3;         // dense-GEMM n-chunk

    for (int l = 0; l < Ln; ++l){
        const float2* WL = g_wpacked + l*LSTRIDE;
        layernorm_rm(X, H, ln1g + l*En, ln1b + l*En, valid);
        __syncthreads();
        {   // fused QKV, rotated tasks; RoPE fused into Q/K epilogues; all rounded
            const int mtq = mtw, mtk = (mtw + 1) & 3, mtv = (mtw + 2) & 3;
            if (mtq*16 < valid)
                mma_tile_p<En, En, SX, SX, 0, 1, 1>(H, WL,         bq + l*En, Qb,
                                                    mtq*16, ncw*32, RC, RS);
            if (mtk*16 < valid)
                mma_tile_p<En, En, SX, SX, 0, 1, 1>(H, WL + 8192,  bk + l*En, Kb,
                                                    mtk*16, ncw*32, RC, RS);
            if (mtv*16 < valid)
                mma_tile_p<En, En, SX, SX, 0, 0, 1>(H, WL + 16384, bv + l*En, Vb,
                                                    mtv*16, ncw*32, RC, RS);
        }
        __syncthreads();
        // zero dead K/V rows (garbage/NaN barrier for attention mma)
        for (int idx = tid; idx < Sn*(En/2); idx += NTHREADS){
            int row = idx >> 6;
            if (row >= valid){
                int c = (idx & 63) << 1;
                Kb[row*SX + c] = 0.f; Kb[row*SX + c + 1] = 0.f;
                Vb[row*SX + c] = 0.f; Vb[row*SX + c + 1] = 0.f;
            }
        }
        __syncthreads();

        // ---- attention via tensor cores; two head-pair passes ----
        for (int hp = 0; hp < 2; hp++){
            {   // S = Q K^T (raw f32 out; operands pre-rounded)
                const int h2 = warp >> 3, mt = (warp >> 1) & 3, nh = warp & 1;
                const int qbase = (hp*2 + h2)*DHn;
                const int m0 = mt*16;
                if (m0 < valid){
                    float dS[4][4];
                    #pragma unroll
                    for (int nt = 0; nt < 4; nt++)
                        dS[nt][0] = dS[nt][1] = dS[nt][2] = dS[nt][3] = 0.f;
                    const float* q0 = Qb + (m0 + g)*SX + qbase;
                    const float* q1 = q0 + 8*SX;
                    #pragma unroll
                    for (int ks = 0; ks < 4; ks++){
                        const int k0 = ks*8;
                        uint32_t ua[4] = { __float_as_uint(q0[k0+tig]),
                                           __float_as_uint(q1[k0+tig]),
                                           __float_as_uint(q0[k0+tig+4]),
                                           __float_as_uint(q1[k0+tig+4]) };
                        #pragma unroll
                        for (int nt = 0; nt < 4; nt++){
                            const int n0 = nh*32 + nt*8;
                            if (n0 < valid){
                                const float* kp = Kb + (n0 + g)*SX + qbase + k0;
                                uint32_t ub[2] = { __float_as_uint(kp[tig]),
                                                   __float_as_uint(kp[tig+4]) };
                                mma_tf32(dS[nt], ua, ub);
                            }
                        }
                    }
                    float* Sp = SS + h2*(Sn*SP);
                    #pragma unroll
                    for (int nt = 0; nt < 4; nt++){
                        const int n0 = nh*32 + nt*8;
                        if (n0 < valid){
                            float* p = Sp + (m0 + g)*SP + n0 + 2*tig;
                            *(float2*)p          = make_float2(dS[nt][0], dS[nt][1]);
                            *(float2*)(p + 8*SP) = make_float2(dS[nt][2], dS[nt][3]);
                        }
                    }
                }
            }
            __syncthreads();
            {   // softmax: normalized + tf32-ROUNDED P; masked cols zeroed
                const int r   = tid >> 2;
                const int q4  = tid & 3;
                const int h2  = r >> 6, row = r & 63;
                if (row < valid){
                    const unsigned gmask = 0xFu << (lane & 28);
                    float* Sr = SS + h2*(Sn*SP) + row*SP;
                    float sv[16];
                    float m = -1e30f;
                    #pragma unroll
                    for (int i = 0; i < 16; i++){
                        int c = q4 + 4*i;
                        if (c < valid){ sv[i] = Sr[c]*scale; m = fmaxf(m, sv[i]); }
                        else sv[i] = 0.f;
                    }
                    m = fmaxf(m, __shfl_xor_sync(gmask, m, 1));
                    m = fmaxf(m, __shfl_xor_sync(gmask, m, 2));
                    float sum = 0.f;
                    #pragma unroll
                    for (int i = 0; i < 16; i++){
                        int c = q4 + 4*i;
                        float e = (c < valid) ? __expf(sv[i] - m) : 0.f;
                        sv[i] = e; sum += e;
                    }
                    sum += __shfl_xor_sync(gmask, sum, 1);
                    sum += __shfl_xor_sync(gmask, sum, 2);
                    const float inv = 1.0f / sum;
                    #pragma unroll
                    for (int i = 0; i < 16; i++) Sr[q4 + 4*i] = rtf(sv[i]*inv);
                }
            }
            __syncthreads();
            {   // O = P V -> H (operands pre-rounded; output rounded for wo GEMM)
                const int h2 = warp >> 3, mt = (warp >> 1) & 3, nh = warp & 1;
                const int obase = (hp*2 + h2)*DHn + nh*16;
                const int m0 = mt*16;
                if (m0 < valid){
                    float dO[2][4];
                    #pragma unroll
                    for (int nt = 0; nt < 2; nt++)
                        dO[nt][0] = dO[nt][1] = dO[nt][2] = dO[nt][3] = 0.f;
                    const float* Pp = SS + h2*(Sn*SP);
                    const float* p0 = Pp + (m0 + g)*SP;
                    const float* p1 = p0 + 8*SP;
                    const int NKS = (valid + 7) >> 3;
                    #pragma unroll 1
                    for (int ks = 0; ks < NKS; ks++){
                        const int k0 = ks*8;
                        uint32_t ua[4] = { __float_as_uint(p0[k0+tig]),
                                           __float_as_uint(p1[k0+tig]),
                                           __float_as_uint(p0[k0+tig+4]),
                                           __float_as_uint(p1[k0+tig+4]) };
                        #pragma unroll
                        for (int nt = 0; nt < 2; nt++){
                            const float* vp = Vb + (k0 + tig)*SX + obase + nt*8 + g;
                            uint32_t ub[2] = { __float_as_uint(vp[0]),
                                               __float_as_uint(vp[4*SX]) };
                            mma_tf32(dO[nt], ua, ub);
                        }
                    }
                    #pragma unroll
                    for (int nt = 0; nt < 2; nt++){
                        const int c = obase + nt*8 + 2*tig;
                        float* p = H + (m0 + g)*SX + c;
                        *(float2*)p          = make_float2(rtf(dO[nt][0]), rtf(dO[nt][1]));
                        *(float2*)(p + 8*SX) = make_float2(rtf(dO[nt][2]), rtf(dO[nt][3]));
                    }
                }
            }
            __syncthreads();
        }

        if (mtw*16 < valid)           // x += o @ wo + bo (X stays full fp32)
            mma_tile_p<En, En, SX, SX, 1, 0, 0>(H, WL + 24576, bo + l*En, X,
                                                mtw*16, ncw*32, RC, RS);
        __syncthreads();
        layernorm_rm(X, H, ln2g + l*En, ln2b + l*En, valid);
        __syncthreads();
        #pragma unroll
        for (int i = 0; i < 2; i++){  // gelu(h2 @ w1 + b1) -> FF (rounded)
            const int mt = (mtw + 2*i) & 3;
            if (mt*16 < valid)
                mma_tile_p<En, FFn, SX, SF, 2, 0, 1>(H, WL + 32768, b1 + l*FFn, FF,
                                                     mt*16, (ncw + 4*i)*32, RC, RS);
        }
        __syncthreads();
        if (mtw*16 < valid)           // x += ff @ w2 + b2
            mma_tile_p<FFn, En, SF, SX, 1, 0, 0>(FF, WL + 49152, b2 + l*En, X,
                                                 mtw*16, ncw*32, RC, RS);
        __syncthreads();
    }

    // Epilogue: out-layernorm rows 0..3, write (B,T,C*E)
    if (warp < Cn){
        const float4 xv = *(const float4*)(X + warp*SX + lane*4);
        float s  = xv.x + xv.y + xv.z + xv.w;
        float s2 = xv.x*xv.x + xv.y*xv.y + xv.z*xv.z + xv.w*xv.w;
        #pragma unroll
        for (int o = 16; o; o >>= 1){
            s  += __shfl_xor_sync(0xffffffffu, s,  o);
            s2 += __shfl_xor_sync(0xffffffffu, s2, o);
        }
        const float m    = s * 0.0078125f;
        const float rstd = rsqrtf(s2*0.0078125f - m*m + 1e-5f);
        const float4 gv  = *(const float4*)(og + lane*4);
        const float4 bv4 = *(const float4*)(ob + lane*4);
        float4 ovv;
        ovv.x = (xv.x - m)*rstd*gv.x + bv4.x;
        ovv.y = (xv.y - m)*rstd*gv.y + bv4.y;
        ovv.z = (xv.z - m)*rstd*gv.z + bv4.z;
        ovv.w = (xv.w - m)*rstd*gv.w + bv4.w;
        *(float4*)(out + (size_t)n*(Cn*En) + warp*En + lane*4) = ovv;
    }
}

extern "C" void kernel_launch(void* const* d_in, const int* in_sizes, int n_in,
                              void* d_out, int out_size)
{
    (void)in_sizes; (void)n_in; (void)out_size;
    prep_weights<<<dim3(32, 18), 256>>>(
        (const float*)d_in[4],  (const float*)d_in[6],  (const float*)d_in[8],
        (const float*)d_in[10], (const float*)d_in[14], (const float*)d_in[16]);
    cudaFuncSetAttribute(rowinteraction_kernel,
                         cudaFuncAttributeMaxDynamicSharedMemorySize, SMEM_BYTES);
    rowinteraction_kernel<<<Bn*Tn, NTHREADS, SMEM_BYTES>>>(
        (const float*)d_in[0],  (const float*)d_in[1],
        (const float*)d_in[2],  (const float*)d_in[3],
        (const float*)d_in[5],  (const float*)d_in[7],
        (const float*)d_in[9],  (const float*)d_in[11],
        (const float*)d_in[12], (const float*)d_in[13],
        (const float*)d_in[15], (const float*)d_in[17],
        (const float*)d_in[18], (const float*)d_in[19],
        (const int*)d_in[20],   (float*)d_out);
}

// round 14
// speedup vs baseline: 1.5650x; 1.0087x over previous
#include <cuda_runtime.h>
#include <math.h>
#include <stdint.h>

#define Bn 4
#define Tn 1024
#define Sn 64
#define En 128
#define NHn 4
#define DHn 32
#define FFn 256
#define Ln 3
#define Cn 4
#define SX 132            // row-major stride; 132 mod 32 = 4 -> conflict-free A-frags
#define SF 260            // FF stride; 260 mod 32 = 4
#define NTHREADS 512

// packed weights: per layer {wq,wk,wv,wo: 8192 each, w1: 16384, w2: 16384} = 65536 float2
#define LSTRIDE 65536
__device__ float2 g_wpacked[3*LSTRIDE];

// ---- tf32 helpers ----
__device__ __forceinline__ uint32_t totf(float f){
    uint32_t u; asm("cvt.rna.tf32.f32 %0, %1;" : "=r"(u) : "f"(f)); return u;
}
__device__ __forceinline__ float rtf(float f){ return __uint_as_float(totf(f)); }
__device__ __forceinline__ void mma_tf32(float d[4], const uint32_t a[4], const uint32_t b[2]){
    asm("mma.sync.aligned.m16n8k8.row.col.f32.tf32.tf32.f32 "
        "{%0,%1,%2,%3},{%4,%5,%6,%7},{%8,%9},{%0,%1,%2,%3};"
        : "+f"(d[0]), "+f"(d[1]), "+f"(d[2]), "+f"(d[3])
        : "r"(a[0]), "r"(a[1]), "r"(a[2]), "r"(a[3]), "r"(b[0]), "r"(b[1]));
}

__device__ __forceinline__ float gelu_tanh(float x){
    float x3 = x*x*x;
    float t = tanhf(0.7978845608028654f*(x + 0.044715f*x3));
    return 0.5f*x*(1.0f + t);
}

// ---- weight prep: tf32-round + fragment-pack. blockIdx.y = l*6 + w ----
__global__ void prep_weights(const float* __restrict__ wq, const float* __restrict__ wk,
                             const float* __restrict__ wv, const float* __restrict__ wo,
                             const float* __restrict__ w1, const float* __restrict__ w2)
{
    const int y = blockIdx.y;
    const int l = y / 6, w = y - 6*l;
    const float* W; int IC, OC; int off;
    switch (w){
        case 0: W = wq + l*En*En;  IC = En;  OC = En;  off = 0;     break;
        case 1: W = wk + l*En*En;  IC = En;  OC = En;  off = 8192;  break;
        case 2: W = wv + l*En*En;  IC = En;  OC = En;  off = 16384; break;
        case 3: W = wo + l*En*En;  IC = En;  OC = En;  off = 24576; break;
        case 4: W = w1 + l*En*FFn; IC = En;  OC = FFn; off = 32768; break;
        default:W = w2 + l*FFn*En; IC = FFn; OC = En;  off = 49152; break;
    }
    const int total = (IC >> 3) * OC * 4;
    float2* dst = g_wpacked + l*LSTRIDE + off;
    for (int idx = blockIdx.x*blockDim.x + threadIdx.x; idx < total;
         idx += gridDim.x*blockDim.x){
        const int tig = idx & 3;
        const int rem = idx >> 2;
        const int n   = rem % OC;
        const int ks  = rem / OC;
        const float a = W[(ks*8 + tig)*OC + n];
        const float b = W[(ks*8 + tig + 4)*OC + n];
        dst[idx] = make_float2(__uint_as_float(totf(a)), __uint_as_float(totf(b)));
    }
}

// ---- layernorm: 8 threads/row; output tf32-rounded; dead rows zeroed ----
__device__ __forceinline__ void layernorm_rm(const float* __restrict__ src,
        float* __restrict__ dst, const float* __restrict__ g,
        const float* __restrict__ b, int valid)
{
    const int t   = threadIdx.x;
    const int row = t >> 3;
    const int e   = t & 7;
    float* dr = dst + row*SX;
    if (row < valid){
        const unsigned gmask = 0xFFu << ((t & 31) & ~7);
        const float* xr = src + row*SX;
        float s = 0.f, s2 = 0.f;
        #pragma unroll
        for (int i = 0; i < 16; i++){
            float v = xr[e + 8*i];
            s += v; s2 = fmaf(v, v, s2);
        }
        s  += __shfl_xor_sync(gmask, s, 1);  s2 += __shfl_xor_sync(gmask, s2, 1);
        s  += __shfl_xor_sync(gmask, s, 2);  s2 += __shfl_xor_sync(gmask, s2, 2);
        s  += __shfl_xor_sync(gmask, s, 4);  s2 += __shfl_xor_sync(gmask, s2, 4);
        const float m    = s * 0.0078125f;
        const float rstd = rsqrtf(s2*0.0078125f - m*m + 1e-5f);
        #pragma unroll
        for (int i = 0; i < 16; i++){
            int c = e + 8*i;
            dr[c] = rtf((xr[c] - m)*rstd*g[c] + b[c]);
        }
    } else {
        #pragma unroll
        for (int i = 0; i < 16; i++) dr[e + 8*i] = 0.f;
    }
}

// ---- tensor-core GEMM warp tile on PACKED weights + PRE-ROUNDED src ----
// MODE 0 = store, 1 = add into dst (fp32), 2 = gelu store.
// ROPE: rotate (j, j+16) head pairs in registers. ROUND: tf32-round stores.
// ZMASK: zero stores for rows >= valid (MODE 0 only).
template<int IC, int OC, int SS, int DS, int MODE, int ROPE, int ROUND, int ZMASK>
__device__ __forceinline__ void mma_tile_p(const float* __restrict__ src,
        const float2* __restrict__ Wp, const float* __restrict__ bias,
        float* __restrict__ dst, int m0, int n0,
        const float* __restrict__ RCp, const float* __restrict__ RSp, int valid)
{
    const int lane = threadIdx.x & 31;
    const int g    = lane >> 2;
    const int tig  = lane & 3;
    const int NK   = IC / 8;

    float d[4][4];
    #pragma unroll
    for (int nt = 0; nt < 4; nt++){
        const float2 bb = *(const float2*)(bias + n0 + nt*8 + 2*tig);
        d[nt][0] = bb.x; d[nt][1] = bb.y; d[nt][2] = bb.x; d[nt][3] = bb.y;
    }

    const float* s0 = src + (m0 + g)*SS + tig;
    const float* s1 = src + (m0 + g + 8)*SS + tig;
    const float2* Wb = Wp + (size_t)(n0 + g)*4 + tig;

    float aC[4]; float2 bC[4];
    aC[0] = s0[0]; aC[1] = s1[0]; aC[2] = s0[4]; aC[3] = s1[4];
    #pragma unroll
    for (int nt = 0; nt < 4; nt++) bC[nt] = __ldg(Wb + nt*32);

    #pragma unroll 1
    for (int ks = 0; ks < NK; ks++){
        const int k1 = (ks + 1 < NK) ? (ks + 1)*8 : ks*8;
        const float2* Wn = Wb + (size_t)((ks + 1 < NK) ? (ks + 1) : ks)*OC*4;
        float aN[4]; float2 bN[4];
        aN[0] = s0[k1]; aN[1] = s1[k1]; aN[2] = s0[k1+4]; aN[3] = s1[k1+4];
        #pragma unroll
        for (int nt = 0; nt < 4; nt++) bN[nt] = __ldg(Wn + nt*32);
        uint32_t ua[4];
        #pragma unroll
        for (int i = 0; i < 4; i++) ua[i] = __float_as_uint(aC[i]);
        #pragma unroll
        for (int nt = 0; nt < 4; nt++){
            uint32_t ub[2] = { __float_as_uint(bC[nt].x), __float_as_uint(bC[nt].y) };
            mma_tf32(d[nt], ua, ub);
        }
        #pragma unroll
        for (int i = 0; i < 4; i++) aC[i] = aN[i];
        #pragma unroll
        for (int nt = 0; nt < 4; nt++) bC[nt] = bN[nt];
    }

    if (ROPE){
        #pragma unroll
        for (int nt = 0; nt < 2; nt++){
            const int j = nt*8 + 2*tig;
            const float2 c0 = *(const float2*)(RCp + (m0 + g)*16 + j);
            const float2 s0v= *(const float2*)(RSp + (m0 + g)*16 + j);
            const float2 c1 = *(const float2*)(RCp + (m0 + g + 8)*16 + j);
            const float2 s1v= *(const float2*)(RSp + (m0 + g + 8)*16 + j);
            float t1, t2;
            t1 = d[nt][0]; t2 = d[nt+2][0];
            d[nt][0] = t1*c0.x - t2*s0v.x;  d[nt+2][0] = t2*c0.x + t1*s0v.x;
            t1 = d[nt][1]; t2 = d[nt+2][1];
            d[nt][1] = t1*c0.y - t2*s0v.y;  d[nt+2][1] = t2*c0.y + t1*s0v.y;
            t1 = d[nt][2]; t2 = d[nt+2][2];
            d[nt][2] = t1*c1.x - t2*s1v.x;  d[nt+2][2] = t2*c1.x + t1*s1v.x;
            t1 = d[nt][3]; t2 = d[nt+2][3];
            d[nt][3] = t1*c1.y - t2*s1v.y;  d[nt+2][3] = t2*c1.y + t1*s1v.y;
        }
    }

    const bool z0 = ZMASK && (m0 + g     >= valid);
    const bool z1 = ZMASK && (m0 + g + 8 >= valid);
    #pragma unroll
    for (int nt = 0; nt < 4; nt++){
        const int c  = n0 + nt*8 + 2*tig;
        float* p0 = dst + (m0 + g)*DS + c;
        float* p1 = dst + (m0 + g + 8)*DS + c;
        if (MODE == 0){
            float v00, v01, v10, v11;
            if (ROUND){ v00=rtf(d[nt][0]); v01=rtf(d[nt][1]); v10=rtf(d[nt][2]); v11=rtf(d[nt][3]); }
            else      { v00=d[nt][0]; v01=d[nt][1]; v10=d[nt][2]; v11=d[nt][3]; }
            if (z0){ v00 = 0.f; v01 = 0.f; }
            if (z1){ v10 = 0.f; v11 = 0.f; }
            *(float2*)p0 = make_float2(v00, v01);
            *(float2*)p1 = make_float2(v10, v11);
        } else if (MODE == 1){
            float2 x0 = *(float2*)p0, x1 = *(float2*)p1;
            x0.x += d[nt][0]; x0.y += d[nt][1]; *(float2*)p0 = x0;
            x1.x += d[nt][2]; x1.y += d[nt][3]; *(float2*)p1 = x1;
        } else {
            *(float2*)p0 = make_float2(rtf(gelu_tanh(d[nt][0])), rtf(gelu_tanh(d[nt][1])));
            *(float2*)p1 = make_float2(rtf(gelu_tanh(d[nt][2])), rtf(gelu_tanh(d[nt][3])));
        }
    }
}

// zero a 16x32 tile region (8 float2 per lane)
__device__ __forceinline__ void zero_tile(float* dst, int m0, int n0){
    const int lane = threadIdx.x & 31;
    const int g = lane >> 2, tig = lane & 3;
    #pragma unroll
    for (int nt = 0; nt < 4; nt++){
        const int c = n0 + nt*8 + 2*tig;
        *(float2*)(dst + (m0 + g)*SX + c)     = make_float2(0.f, 0.f);
        *(float2*)(dst + (m0 + g + 8)*SX + c) = make_float2(0.f, 0.f);
    }
}

#define SMEM_FLOATS (5*Sn*SX + 2*Sn*16)
#define SMEM_BYTES  (SMEM_FLOATS*4)

__global__ void __launch_bounds__(NTHREADS, 1) rowinteraction_kernel(
    const float* __restrict__ emb,  const float* __restrict__ cls,
    const float* __restrict__ ln1g, const float* __restrict__ ln1b,
    const float* __restrict__ bq,   const float* __restrict__ bk,
    const float* __restrict__ bv,   const float* __restrict__ bo,
    const float* __restrict__ ln2g, const float* __restrict__ ln2b,
    const float* __restrict__ b1,   const float* __restrict__ b2,
    const float* __restrict__ og,   const float* __restrict__ ob,
    const int*   __restrict__ dvec, float* __restrict__ out)
{
    extern __shared__ float smf[];
    float* X  = smf;                 // [64][132] residual (fp32)
    float* H  = X  + Sn*SX;          // [64][132] ln/attn out (tf32-rounded)
    float* Qb = H  + Sn*SX;
    float* Kb = Qb + Sn*SX;
    float* Vb = Kb + Sn*SX;
    float* FF = Qb;                  // [64][260] overlays Q+K
    float* RC = Vb + Sn*SX;          // rope cos [64][16]
    float* RS = RC + Sn*16;

    const int tid   = threadIdx.x;
    const int warp  = tid >> 5;
    const int lane  = tid & 31;
    const int g     = lane >> 2;
    const int tig   = lane & 3;
    const int n     = blockIdx.x;
    const int bidx  = n >> 10;        // T = 1024
    const int valid = dvec[bidx] + Cn;          // 4..63
    const float scale = 0.17677669529663687f;   // 1/sqrt(32)

    for (int idx = tid; idx < Sn*16; idx += NTHREADS){
        int pos = idx >> 4, f = idx & 15;
        float inv = expf(-((float)(2*f) / (float)DHn) * logf(100000.0f));
        float ang = (float)pos * inv;
        RC[idx] = cosf(ang); RS[idx] = sinf(ang);
    }
    for (int idx = tid; idx < Sn*En; idx += NTHREADS){
        int r = idx >> 7, c = idx & 127;
        float v = (r < Cn) ? cls[r*En + c] : emb[((size_t)n*Sn + r)*En + c];
        X[r*SX + c] = v;
    }
    __syncthreads();

    const int mtw = warp >> 2;        // dense-GEMM m-tile
    const int ncw = warp & 3;         // dense-GEMM n-chunk

    for (int l = 0; l < Ln; ++l){
        const float2* WL = g_wpacked + l*LSTRIDE;
        layernorm_rm(X, H, ln1g + l*En, ln1b + l*En, valid);
        __syncthreads();
        {   // fused QKV (rotated tasks) + RoPE + dead K/V zeroing, ONE phase
            const int mtq = mtw, mtk = (mtw + 1) & 3, mtv = (mtw + 2) & 3;
            if (mtq*16 < valid)
                mma_tile_p<En, En, SX, SX, 0, 1, 1, 0>(H, WL,         bq + l*En, Qb,
                                                       mtq*16, ncw*32, RC, RS, valid);
            if (mtk*16 < valid)
                mma_tile_p<En, En, SX, SX, 0, 1, 1, 1>(H, WL + 8192,  bk + l*En, Kb,
                                                       mtk*16, ncw*32, RC, RS, valid);
            else zero_tile(Kb, mtk*16, ncw*32);
            if (mtv*16 < valid)
                mma_tile_p<En, En, SX, SX, 0, 0, 1, 1>(H, WL + 16384, bv + l*En, Vb,
                                                       mtv*16, ncw*32, RC, RS, valid);
            else zero_tile(Vb, mtv*16, ncw*32);
        }
        __syncthreads();

        // ---- warp-local attention: warp = (head, m-tile); S, softmax, PV
        //      all in registers; zero intra-attention barriers ----
        {
            const int head = warp >> 2;
            const int amt  = warp & 3;
            const int m0   = amt*16;
            const int qbase= head*DHn;
            if (m0 < valid){
                const int NKS = (valid + 7) >> 3;   // live 8-col/row blocks
                float dS[8][4];
                #pragma unroll
                for (int nt = 0; nt < 8; nt++)
                    dS[nt][0] = dS[nt][1] = dS[nt][2] = dS[nt][3] = 0.f;
                const float* q0 = Qb + (m0 + g)*SX + qbase;
                const float* q1 = q0 + 8*SX;
                #pragma unroll
                for (int ks = 0; ks < 4; ks++){
                    const int k0 = ks*8;
                    uint32_t ua[4] = { __float_as_uint(q0[k0+tig]),
                                       __float_as_uint(q1[k0+tig]),
                                       __float_as_uint(q0[k0+tig+4]),
                                       __float_as_uint(q1[k0+tig+4]) };
                    #pragma unroll
                    for (int nt = 0; nt < 8; nt++){
                        if (nt < NKS){
                            const float* kp = Kb + (nt*8 + g)*SX + qbase + k0;
                            uint32_t ub[2] = { __float_as_uint(kp[tig]),
                                               __float_as_uint(kp[tig+4]) };
                            mma_tf32(dS[nt], ua, ub);
                        }
                    }
                }
                // in-register softmax; rows r0 = m0+g (comp 0,1), r1 = m0+g+8 (comp 2,3)
                float mx0 = -1e30f, mx1 = -1e30f;
                #pragma unroll
                for (int nt = 0; nt < 8; nt++){
                    #pragma unroll
                    for (int c2 = 0; c2 < 2; c2++){
                        if (nt*8 + 2*tig + c2 < valid){
                            mx0 = fmaxf(mx0, dS[nt][c2]);
                            mx1 = fmaxf(mx1, dS[nt][2+c2]);
                        }
                    }
                }
                mx0 = fmaxf(mx0, __shfl_xor_sync(0xffffffffu, mx0, 1));
                mx0 = fmaxf(mx0, __shfl_xor_sync(0xffffffffu, mx0, 2));
                mx1 = fmaxf(mx1, __shfl_xor_sync(0xffffffffu, mx1, 1));
                mx1 = fmaxf(mx1, __shfl_xor_sync(0xffffffffu, mx1, 2));
                mx0 *= scale; mx1 *= scale;
                float sm0 = 0.f, sm1 = 0.f;
                #pragma unroll
                for (int nt = 0; nt < 8; nt++){
                    #pragma unroll
                    for (int c2 = 0; c2 < 2; c2++){
                        const bool live = (nt*8 + 2*tig + c2 < valid);
                        float e0 = live ? __expf(dS[nt][c2]*scale   - mx0) : 0.f;
                        float e1 = live ? __expf(dS[nt][2+c2]*scale - mx1) : 0.f;
                        dS[nt][c2]   = e0; sm0 += e0;
                        dS[nt][2+c2] = e1; sm1 += e1;
                    }
                }
                sm0 += __shfl_xor_sync(0xffffffffu, sm0, 1);
                sm0 += __shfl_xor_sync(0xffffffffu, sm0, 2);
                sm1 += __shfl_xor_sync(0xffffffffu, sm1, 1);
                sm1 += __shfl_xor_sync(0xffffffffu, sm1, 2);
                const float iv0 = 1.0f / sm0, iv1 = 1.0f / sm1;
                #pragma unroll
                for (int nt = 0; nt < 8; nt++){
                    dS[nt][0] = rtf(dS[nt][0]*iv0);
                    dS[nt][1] = rtf(dS[nt][1]*iv0);
                    dS[nt][2] = rtf(dS[nt][2]*iv1);
                    dS[nt][3] = rtf(dS[nt][3]*iv1);
                }
                // PV: A-frags assembled from P (dS) by in-group shuffle
                float dO[4][4];
                #pragma unroll
                for (int nt = 0; nt < 4; nt++)
                    dO[nt][0] = dO[nt][1] = dO[nt][2] = dO[nt][3] = 0.f;
                const int srcl = g*4 + (tig >> 1);
                const bool hi  = (tig & 1);
                #pragma unroll
                for (int ks = 0; ks < 8; ks++){
                    if (ks < NKS){
                        float v0, v1;
                        v0 = __shfl_sync(0xffffffffu, dS[ks][0], srcl);
                        v1 = __shfl_sync(0xffffffffu, dS[ks][1], srcl);
                        const float a0 = hi ? v1 : v0;
                        v0 = __shfl_sync(0xffffffffu, dS[ks][2], srcl);
                        v1 = __shfl_sync(0xffffffffu, dS[ks][3], srcl);
                        const float a1 = hi ? v1 : v0;
                        v0 = __shfl_sync(0xffffffffu, dS[ks][0], srcl + 2);
                        v1 = __shfl_sync(0xffffffffu, dS[ks][1], srcl + 2);
                        const float a2 = hi ? v1 : v0;
                        v0 = __shfl_sync(0xffffffffu, dS[ks][2], srcl + 2);
                        v1 = __shfl_sync(0xffffffffu, dS[ks][3], srcl + 2);
                        const float a3 = hi ? v1 : v0;
                        uint32_t ua[4] = { __float_as_uint(a0), __float_as_uint(a1),
                                           __float_as_uint(a2), __float_as_uint(a3) };
                        const int k0 = ks*8;
                        #pragma unroll
                        for (int nt = 0; nt < 4; nt++){
                            const float* vp = Vb + (k0 + tig)*SX + qbase + nt*8 + g;
                            uint32_t ub[2] = { __float_as_uint(vp[0]),
                                               __float_as_uint(vp[4*SX]) };
                            mma_tf32(dO[nt], ua, ub);
                        }
                    }
                }
                #pragma unroll
                for (int nt = 0; nt < 4; nt++){
                    const int c = qbase + nt*8 + 2*tig;
                    float* p = H + (m0 + g)*SX + c;
                    *(float2*)p          = make_float2(rtf(dO[nt][0]), rtf(dO[nt][1]));
                    *(float2*)(p + 8*SX) = make_float2(rtf(dO[nt][2]), rtf(dO[nt][3]));
                }
            }
        }
        __syncthreads();

        if (mtw*16 < valid)           // x += o @ wo + bo
            mma_tile_p<En, En, SX, SX, 1, 0, 0, 0>(H, WL + 24576, bo + l*En, X,
                                                   mtw*16, ncw*32, RC, RS, valid);
        __syncthreads();
        layernorm_rm(X, H, ln2g + l*En, ln2b + l*En, valid);
        __syncthreads();
        #pragma unroll
        for (int i = 0; i < 2; i++){  // gelu(h2 @ w1 + b1) -> FF
            const int mt = (mtw + 2*i) & 3;
            if (mt*16 < valid)
                mma_tile_p<En, FFn, SX, SF, 2, 0, 1, 0>(H, WL + 32768, b1 + l*FFn, FF,
                                                        mt*16, (ncw + 4*i)*32, RC, RS, valid);
        }
        __syncthreads();
        if (mtw*16 < valid)           // x += ff @ w2 + b2
            mma_tile_p<FFn, En, SF, SX, 1, 0, 0, 0>(FF, WL + 49152, b2 + l*En, X,
                                                    mtw*16, ncw*32, RC, RS, valid);
        __syncthreads();
    }

    // Epilogue: out-layernorm rows 0..3, write (B,T,C*E)
    if (warp < Cn){
        const float4 xv = *(const float4*)(X + warp*SX + lane*4);
        float s  = xv.x + xv.y + xv.z + xv.w;
        float s2 = xv.x*xv.x + xv.y*xv.y + xv.z*xv.z + xv.w*xv.w;
        #pragma unroll
        for (int o = 16; o; o >>= 1){
            s  += __shfl_xor_sync(0xffffffffu, s,  o);
            s2 += __shfl_xor_sync(0xffffffffu, s2, o);
        }
        const float m    = s * 0.0078125f;
        const float rstd = rsqrtf(s2*0.0078125f - m*m + 1e-5f);
        const float4 gv  = *(const float4*)(og + lane*4);
        const float4 bv4 = *(const float4*)(ob + lane*4);
        float4 ovv;
        ovv.x = (xv.x - m)*rstd*gv.x + bv4.x;
        ovv.y = (xv.y - m)*rstd*gv.y + bv4.y;
        ovv.z = (xv.z - m)*rstd*gv.z + bv4.z;
        ovv.w = (xv.w - m)*rstd*gv.w + bv4.w;
        *(float4*)(out + (size_t)n*(Cn*En) + warp*En + lane*4) = ovv;
    }
}

extern "C" void kernel_launch(void* const* d_in, const int* in_sizes, int n_in,
                              void* d_out, int out_size)
{
    (void)in_sizes; (void)n_in; (void)out_size;
    prep_weights<<<dim3(32, 18), 256>>>(
        (const float*)d_in[4],  (const float*)d_in[6],  (const float*)d_in[8],
        (const float*)d_in[10], (const float*)d_in[14], (const float*)d_in[16]);
    cudaFuncSetAttribute(rowinteraction_kernel,
                         cudaFuncAttributeMaxDynamicSharedMemorySize, SMEM_BYTES);
    rowinteraction_kernel<<<Bn*Tn, NTHREADS, SMEM_BYTES>>>(
        (const float*)d_in[0],  (const float*)d_in[1],
        (const float*)d_in[2],  (const float*)d_in[3],
        (const float*)d_in[5],  (const float*)d_in[7],
        (const float*)d_in[9],  (const float*)d_in[11],
        (const float*)d_in[12], (const float*)d_in[13],
        (const float*)d_in[15], (const float*)d_in[17],
        (const float*)d_in[18], (const float*)d_in[19],
        (const int*)d_in[20],   (float*)d_out);
}